// round 3
// baseline (speedup 1.0000x reference)
#include <cuda_runtime.h>

#define B_ 2
#define N_ 4096
#define C_ 512
#define H_ 8
#define D_ 64
#define SCALE_ 0.125f

// Scratch (allocation-free rule: __device__ globals)
__device__ float g_Q[B_*H_*N_*D_];
__device__ float g_K[B_*H_*N_*D_];
__device__ float g_V[B_*H_*N_*D_];
__device__ float g_X[B_*N_*C_];

// ---------------------------------------------------------------------------
// Projection GEMM: Out(r, c) = sum_k A(r, k) * W(c, k)   (A row-major 8192x512,
// W row-major 512x512). 64x64 tile per CTA, 256 threads, 4x4 microtile.
// Smem tiles stored transposed [k][m] so compute reads are float4 +
// conflict-free (consecutive tx -> consecutive addresses).
// Output written in (B, H, N, D) head-major layout for the attention stage.
// ---------------------------------------------------------------------------
__global__ __launch_bounds__(256) void proj_qkv_kernel(
    const float* __restrict__ qin, const float* __restrict__ kin,
    const float* __restrict__ vin, const float* __restrict__ Wq,
    const float* __restrict__ Wk,  const float* __restrict__ Wv)
{
    const int which = blockIdx.z;
    const float* A = (which == 0) ? qin : (which == 1) ? kin : vin;
    const float* W = (which == 0) ? Wq  : (which == 1) ? Wk  : Wv;
    float* Out     = (which == 0) ? g_Q : (which == 1) ? g_K : g_V;

    const int r0 = blockIdx.y * 64;   // flat row base over B*N = 8192
    const int hx = blockIdx.x;        // head index (64 cols per head)

    __shared__ float As[32 * 68];
    __shared__ float Ws[32 * 68];

    const int tid = threadIdx.x;
    const int ty = tid >> 4, tx = tid & 15;

    float acc[4][4];
    #pragma unroll
    for (int i = 0; i < 4; i++)
        #pragma unroll
        for (int j = 0; j < 4; j++) acc[i][j] = 0.f;

    for (int k0 = 0; k0 < C_; k0 += 32) {
        #pragma unroll
        for (int e = tid; e < 512; e += 256) {
            int row = e >> 3;            // 0..63
            int kq  = (e & 7) << 2;      // 0,4,...,28
            float4 a4 = *(const float4*)&A[(r0 + row) * C_ + k0 + kq];
            As[(kq + 0) * 68 + row] = a4.x;
            As[(kq + 1) * 68 + row] = a4.y;
            As[(kq + 2) * 68 + row] = a4.z;
            As[(kq + 3) * 68 + row] = a4.w;
            float4 w4 = *(const float4*)&W[(hx * 64 + row) * C_ + k0 + kq];
            Ws[(kq + 0) * 68 + row] = w4.x;
            Ws[(kq + 1) * 68 + row] = w4.y;
            Ws[(kq + 2) * 68 + row] = w4.z;
            Ws[(kq + 3) * 68 + row] = w4.w;
        }
        __syncthreads();
        #pragma unroll 8
        for (int kk = 0; kk < 32; kk++) {
            float4 a4 = *(const float4*)&As[kk * 68 + ty * 4];
            float4 b4 = *(const float4*)&Ws[kk * 68 + tx * 4];
            float av[4] = {a4.x, a4.y, a4.z, a4.w};
            float bv[4] = {b4.x, b4.y, b4.z, b4.w};
            #pragma unroll
            for (int i = 0; i < 4; i++)
                #pragma unroll
                for (int j = 0; j < 4; j++)
                    acc[i][j] = fmaf(av[i], bv[j], acc[i][j]);
        }
        __syncthreads();
    }

    #pragma unroll
    for (int i = 0; i < 4; i++) {
        int r  = r0 + ty * 4 + i;
        int bb = r >> 12;        // / N_
        int n  = r & (N_ - 1);
        float4 o4 = make_float4(acc[i][0], acc[i][1], acc[i][2], acc[i][3]);
        *(float4*)&Out[(((bb * H_ + hx) * N_) + n) * D_ + tx * 4] = o4;
    }
}

// ---------------------------------------------------------------------------
// Flash attention: per (b,h), 64 query rows per CTA, stream 64-row KV tiles,
// online softmax in fp32. Q/K stored d-major in smem ([d][row]) so the
// S-GEMM reads are float4 + conflict-free; P stored transposed [j][row].
// ---------------------------------------------------------------------------
__global__ __launch_bounds__(256) void attn_kernel()
{
    extern __shared__ float sm[];
    float* Qts = sm;                 // [64 d][68]
    float* Kts = sm + 64 * 68;       // [64 d][68]
    float* Vs  = sm + 2 * 64 * 68;   // [64 m][68]
    float* Pts = sm + 3 * 64 * 68;   // [64 j][68]

    const int bh = blockIdx.y;
    const float* Qp = g_Q + bh * (N_ * D_);
    const float* Kp = g_K + bh * (N_ * D_);
    const float* Vp = g_V + bh * (N_ * D_);
    const int n0 = blockIdx.x * 64;
    const int tid = threadIdx.x;
    const int ty = tid >> 4, tx = tid & 15;

    // Load Q tile, transposed + pre-scaled
    #pragma unroll
    for (int e = tid; e < 1024; e += 256) {
        int row = e >> 4;
        int dq  = (e & 15) << 2;
        float4 v = *(const float4*)&Qp[(n0 + row) * D_ + dq];
        Qts[(dq + 0) * 68 + row] = v.x * SCALE_;
        Qts[(dq + 1) * 68 + row] = v.y * SCALE_;
        Qts[(dq + 2) * 68 + row] = v.z * SCALE_;
        Qts[(dq + 3) * 68 + row] = v.w * SCALE_;
    }

    float m_i[4], l_i[4], o[4][4];
    #pragma unroll
    for (int i = 0; i < 4; i++) {
        m_i[i] = -1e30f;
        l_i[i] = 0.f;
        #pragma unroll
        for (int c = 0; c < 4; c++) o[i][c] = 0.f;
    }
    __syncthreads();

    for (int m0 = 0; m0 < N_; m0 += 64) {
        // Load K (transposed) and V (row-major) tiles
        #pragma unroll
        for (int e = tid; e < 1024; e += 256) {
            int row = e >> 4;
            int dq  = (e & 15) << 2;
            float4 kv = *(const float4*)&Kp[(m0 + row) * D_ + dq];
            Kts[(dq + 0) * 68 + row] = kv.x;
            Kts[(dq + 1) * 68 + row] = kv.y;
            Kts[(dq + 2) * 68 + row] = kv.z;
            Kts[(dq + 3) * 68 + row] = kv.w;
            float4 vv = *(const float4*)&Vp[(m0 + row) * D_ + dq];
            *(float4*)&Vs[row * 68 + dq] = vv;
        }
        __syncthreads();

        // S = Q K^T (scaled)
        float s[4][4];
        #pragma unroll
        for (int i = 0; i < 4; i++)
            #pragma unroll
            for (int j = 0; j < 4; j++) s[i][j] = 0.f;
        #pragma unroll 8
        for (int d = 0; d < 64; d++) {
            float4 q4 = *(const float4*)&Qts[d * 68 + ty * 4];
            float4 k4 = *(const float4*)&Kts[d * 68 + tx * 4];
            float qv[4] = {q4.x, q4.y, q4.z, q4.w};
            float kv[4] = {k4.x, k4.y, k4.z, k4.w};
            #pragma unroll
            for (int i = 0; i < 4; i++)
                #pragma unroll
                for (int j = 0; j < 4; j++)
                    s[i][j] = fmaf(qv[i], kv[j], s[i][j]);
        }

        // Online softmax (row stats reduced across the 16 tx lanes)
        #pragma unroll
        for (int i = 0; i < 4; i++) {
            float mx = fmaxf(fmaxf(s[i][0], s[i][1]), fmaxf(s[i][2], s[i][3]));
            #pragma unroll
            for (int off = 8; off >= 1; off >>= 1)
                mx = fmaxf(mx, __shfl_xor_sync(0xffffffffu, mx, off));
            float mn = fmaxf(m_i[i], mx);
            float alpha = __expf(m_i[i] - mn);
            m_i[i] = mn;
            float rs = 0.f;
            #pragma unroll
            for (int j = 0; j < 4; j++) {
                s[i][j] = __expf(s[i][j] - mn);
                rs += s[i][j];
            }
            #pragma unroll
            for (int off = 8; off >= 1; off >>= 1)
                rs += __shfl_xor_sync(0xffffffffu, rs, off);
            l_i[i] = l_i[i] * alpha + rs;
            #pragma unroll
            for (int c = 0; c < 4; c++) o[i][c] *= alpha;
            #pragma unroll
            for (int j = 0; j < 4; j++)
                Pts[(tx * 4 + j) * 68 + ty * 4 + i] = s[i][j];
        }
        __syncthreads();

        // O += P V
        #pragma unroll 8
        for (int j = 0; j < 64; j++) {
            float4 p4 = *(const float4*)&Pts[j * 68 + ty * 4];
            float4 v4 = *(const float4*)&Vs[j * 68 + tx * 4];
            float pv[4] = {p4.x, p4.y, p4.z, p4.w};
            float vv[4] = {v4.x, v4.y, v4.z, v4.w};
            #pragma unroll
            for (int i = 0; i < 4; i++)
                #pragma unroll
                for (int c = 0; c < 4; c++)
                    o[i][c] = fmaf(pv[i], vv[c], o[i][c]);
        }
        __syncthreads();
    }

    const int b = bh / H_, h = bh % H_;
    #pragma unroll
    for (int i = 0; i < 4; i++) {
        float inv = 1.f / l_i[i];
        float4 r = make_float4(o[i][0] * inv, o[i][1] * inv,
                               o[i][2] * inv, o[i][3] * inv);
        int rg = n0 + ty * 4 + i;
        *(float4*)&g_X[(b * N_ + rg) * C_ + h * D_ + tx * 4] = r;
    }
}

// ---------------------------------------------------------------------------
// Output projection: out = X @ Wp^T + bp  (row-major output)
// ---------------------------------------------------------------------------
__global__ __launch_bounds__(256) void proj_out_kernel(
    const float* __restrict__ Wp, const float* __restrict__ bp,
    float* __restrict__ out)
{
    const int r0 = blockIdx.y * 64;
    const int cb = blockIdx.x * 64;

    __shared__ float As[32 * 68];
    __shared__ float Ws[32 * 68];

    const int tid = threadIdx.x;
    const int ty = tid >> 4, tx = tid & 15;

    float acc[4][4];
    #pragma unroll
    for (int i = 0; i < 4; i++)
        #pragma unroll
        for (int j = 0; j < 4; j++) acc[i][j] = 0.f;

    for (int k0 = 0; k0 < C_; k0 += 32) {
        #pragma unroll
        for (int e = tid; e < 512; e += 256) {
            int row = e >> 3;
            int kq  = (e & 7) << 2;
            float4 a4 = *(const float4*)&g_X[(r0 + row) * C_ + k0 + kq];
            As[(kq + 0) * 68 + row] = a4.x;
            As[(kq + 1) * 68 + row] = a4.y;
            As[(kq + 2) * 68 + row] = a4.z;
            As[(kq + 3) * 68 + row] = a4.w;
            float4 w4 = *(const float4*)&Wp[(cb + row) * C_ + k0 + kq];
            Ws[(kq + 0) * 68 + row] = w4.x;
            Ws[(kq + 1) * 68 + row] = w4.y;
            Ws[(kq + 2) * 68 + row] = w4.z;
            Ws[(kq + 3) * 68 + row] = w4.w;
        }
        __syncthreads();
        #pragma unroll 8
        for (int kk = 0; kk < 32; kk++) {
            float4 a4 = *(const float4*)&As[kk * 68 + ty * 4];
            float4 b4 = *(const float4*)&Ws[kk * 68 + tx * 4];
            float av[4] = {a4.x, a4.y, a4.z, a4.w};
            float bv[4] = {b4.x, b4.y, b4.z, b4.w};
            #pragma unroll
            for (int i = 0; i < 4; i++)
                #pragma unroll
                for (int j = 0; j < 4; j++)
                    acc[i][j] = fmaf(av[i], bv[j], acc[i][j]);
        }
        __syncthreads();
    }

    float4 bb = *(const float4*)&bp[cb + tx * 4];
    float bv[4] = {bb.x, bb.y, bb.z, bb.w};
    #pragma unroll
    for (int i = 0; i < 4; i++) {
        int r = r0 + ty * 4 + i;
        float4 o4 = make_float4(acc[i][0] + bv[0], acc[i][1] + bv[1],
                                acc[i][2] + bv[2], acc[i][3] + bv[3]);
        *(float4*)&out[r * C_ + cb + tx * 4] = o4;
    }
}

extern "C" void kernel_launch(void* const* d_in, const int* in_sizes, int n_in,
                              void* d_out, int out_size)
{
    const float* query = (const float*)d_in[0];
    const float* key   = (const float*)d_in[1];
    const float* value = (const float*)d_in[2];
    const float* Wq    = (const float*)d_in[3];
    const float* Wk    = (const float*)d_in[4];
    const float* Wv    = (const float*)d_in[5];
    const float* Wp    = (const float*)d_in[6];
    const float* bp    = (const float*)d_in[7];
    float* out = (float*)d_out;

    const int attn_smem = 4 * 64 * 68 * (int)sizeof(float);  // 69632 B
    cudaFuncSetAttribute(attn_kernel,
                         cudaFuncAttributeMaxDynamicSharedMemorySize, attn_smem);

    dim3 blk(256);
    proj_qkv_kernel<<<dim3(8, 128, 3), blk>>>(query, key, value, Wq, Wk, Wv);
    attn_kernel<<<dim3(64, 16), blk, attn_smem>>>();
    proj_out_kernel<<<dim3(8, 128), blk>>>(Wp, bp, out);
}

// round 4
// speedup vs baseline: 3.0452x; 3.0452x over previous
#include <cuda_runtime.h>

#define B_ 2
#define N_ 4096
#define C_ 512
#define H_ 8
#define D_ 64
#define SCALE_ 0.125f

// Scratch (allocation-free rule: __device__ globals)
__device__ float g_Q[B_*H_*N_*D_];
__device__ float g_K[B_*H_*N_*D_];
__device__ float g_V[B_*H_*N_*D_];
__device__ float g_X[B_*N_*C_];

// ---------------------------------------------------------------------------
// tf32 helpers
// ---------------------------------------------------------------------------
__device__ __forceinline__ unsigned f2tf(float x) {
    unsigned r;
    asm("cvt.rna.tf32.f32 %0, %1;" : "=r"(r) : "f"(x));
    return r;
}

__device__ __forceinline__ void mma8(float* d, const unsigned* a, const unsigned* b) {
    asm volatile(
        "mma.sync.aligned.m16n8k8.row.col.f32.tf32.tf32.f32 "
        "{%0,%1,%2,%3},{%4,%5,%6,%7},{%8,%9},{%0,%1,%2,%3};"
        : "+f"(d[0]), "+f"(d[1]), "+f"(d[2]), "+f"(d[3])
        : "r"(a[0]), "r"(a[1]), "r"(a[2]), "r"(a[3]), "r"(b[0]), "r"(b[1]));
}

// ---------------------------------------------------------------------------
// QKV projection: Out(r,c) = sum_k A(r,k) * W(c,k).  CTA = 128 rows x 64 cols
// (one head's columns). 8 warps, each warp = 16 rows x 64 cols.
// Smem tiles [row][k] with ld=36 (== 4 mod 32 -> conflict-free frag loads).
// Output written head-major (B,H,N,D).
// ---------------------------------------------------------------------------
__global__ __launch_bounds__(256) void proj_qkv_kernel(
    const float* __restrict__ qin, const float* __restrict__ kin,
    const float* __restrict__ vin, const float* __restrict__ Wq,
    const float* __restrict__ Wk,  const float* __restrict__ Wv)
{
    const int which = blockIdx.z;
    const float* A = (which == 0) ? qin : (which == 1) ? kin : vin;
    const float* W = (which == 0) ? Wq  : (which == 1) ? Wk  : Wv;
    float* Out     = (which == 0) ? g_Q : (which == 1) ? g_K : g_V;

    const int r0 = blockIdx.y * 128;
    const int hx = blockIdx.x;

    __shared__ unsigned Asu[128 * 36];
    __shared__ unsigned Wsu[64 * 36];

    const int tid  = threadIdx.x;
    const int warp = tid >> 5;
    const int lane = tid & 31;
    const int qr = lane >> 2, qc = lane & 3;

    float acc[8][4];
    #pragma unroll
    for (int nt = 0; nt < 8; nt++)
        #pragma unroll
        for (int j = 0; j < 4; j++) acc[nt][j] = 0.f;

    for (int k0 = 0; k0 < C_; k0 += 32) {
        #pragma unroll
        for (int i = 0; i < 4; i++) {
            int idx = tid + i * 256;
            int row = idx >> 3, kq = (idx & 7) << 2;
            float4 v = *(const float4*)&A[(r0 + row) * C_ + k0 + kq];
            uint4 t = make_uint4(f2tf(v.x), f2tf(v.y), f2tf(v.z), f2tf(v.w));
            *(uint4*)&Asu[row * 36 + kq] = t;
        }
        #pragma unroll
        for (int i = 0; i < 2; i++) {
            int idx = tid + i * 256;
            int row = idx >> 3, kq = (idx & 7) << 2;
            float4 v = *(const float4*)&W[(hx * 64 + row) * C_ + k0 + kq];
            uint4 t = make_uint4(f2tf(v.x), f2tf(v.y), f2tf(v.z), f2tf(v.w));
            *(uint4*)&Wsu[row * 36 + kq] = t;
        }
        __syncthreads();

        #pragma unroll
        for (int ks = 0; ks < 4; ks++) {
            unsigned a[4];
            int ar = warp * 16 + qr;
            a[0] = Asu[ar * 36 + ks * 8 + qc];
            a[1] = Asu[(ar + 8) * 36 + ks * 8 + qc];
            a[2] = Asu[ar * 36 + ks * 8 + qc + 4];
            a[3] = Asu[(ar + 8) * 36 + ks * 8 + qc + 4];
            #pragma unroll
            for (int nt = 0; nt < 8; nt++) {
                unsigned b[2];
                b[0] = Wsu[(nt * 8 + qr) * 36 + ks * 8 + qc];
                b[1] = Wsu[(nt * 8 + qr) * 36 + ks * 8 + qc + 4];
                mma8(acc[nt], a, b);
            }
        }
        __syncthreads();
    }

    // Write C fragments to head-major output
    const int row0 = r0 + warp * 16 + qr;
    const int row1 = row0 + 8;
    const int b0g = row0 >> 12, n0g = row0 & (N_ - 1);
    const int b1g = row1 >> 12, n1g = row1 & (N_ - 1);
    float* O0 = &Out[(((b0g * H_ + hx) * N_) + n0g) * D_];
    float* O1 = &Out[(((b1g * H_ + hx) * N_) + n1g) * D_];
    #pragma unroll
    for (int nt = 0; nt < 8; nt++) {
        int col = nt * 8 + 2 * qc;
        *(float2*)&O0[col] = make_float2(acc[nt][0], acc[nt][1]);
        *(float2*)&O1[col] = make_float2(acc[nt][2], acc[nt][3]);
    }
}

// ---------------------------------------------------------------------------
// Flash attention on tensor cores. CTA = 128 query rows, KV tiles of 64.
// Q held in registers as tf32 A-fragments. K staged [kv][68] (conflict-free
// B-frag loads), V staged transposed [d][68], P staged [128][68].
// P is produced and consumed by the same warp -> __syncwarp only.
// ---------------------------------------------------------------------------
__global__ __launch_bounds__(256) void attn_kernel()
{
    extern __shared__ unsigned sm[];
    unsigned* Kt = sm;              // [64][68]
    unsigned* Vt = sm + 64 * 68;    // [64][68]  Vt[d][kv]
    unsigned* Ps = sm + 2 * 64 * 68;// [128][68]

    const int bh = blockIdx.y;
    const float* Qp = g_Q + bh * (N_ * D_);
    const float* Kp = g_K + bh * (N_ * D_);
    const float* Vp = g_V + bh * (N_ * D_);
    const int n0 = blockIdx.x * 128;

    const int tid  = threadIdx.x;
    const int warp = tid >> 5;
    const int lane = tid & 31;
    const int qr = lane >> 2, qc = lane & 3;

    // Q fragments (pre-scaled), rows warp*16+qr and +8
    unsigned qa[8][4];
    {
        const float* Q0 = &Qp[(n0 + warp * 16 + qr) * D_];
        const float* Q1 = Q0 + 8 * D_;
        #pragma unroll
        for (int ks = 0; ks < 8; ks++) {
            qa[ks][0] = f2tf(Q0[ks * 8 + qc] * SCALE_);
            qa[ks][1] = f2tf(Q1[ks * 8 + qc] * SCALE_);
            qa[ks][2] = f2tf(Q0[ks * 8 + qc + 4] * SCALE_);
            qa[ks][3] = f2tf(Q1[ks * 8 + qc + 4] * SCALE_);
        }
    }

    float o[8][4];
    #pragma unroll
    for (int nt = 0; nt < 8; nt++)
        #pragma unroll
        for (int j = 0; j < 4; j++) o[nt][j] = 0.f;
    float mrow[2] = {-1e30f, -1e30f};
    float lrow[2] = {0.f, 0.f};

    for (int m0 = 0; m0 < N_; m0 += 64) {
        __syncthreads();   // protect K/V tiles from previous iteration readers
        #pragma unroll
        for (int i = 0; i < 4; i++) {
            int e = tid + i * 256;
            int kv = e >> 4, dq = (e & 15) << 2;
            float4 kvv = *(const float4*)&Kp[(m0 + kv) * D_ + dq];
            *(uint4*)&Kt[kv * 68 + dq] =
                make_uint4(f2tf(kvv.x), f2tf(kvv.y), f2tf(kvv.z), f2tf(kvv.w));
            float4 vv = *(const float4*)&Vp[(m0 + kv) * D_ + dq];
            Vt[(dq + 0) * 68 + kv] = f2tf(vv.x);
            Vt[(dq + 1) * 68 + kv] = f2tf(vv.y);
            Vt[(dq + 2) * 68 + kv] = f2tf(vv.z);
            Vt[(dq + 3) * 68 + kv] = f2tf(vv.w);
        }
        __syncthreads();

        // S = Q K^T  (16 rows x 64 kv per warp)
        float s[8][4];
        #pragma unroll
        for (int nt = 0; nt < 8; nt++)
            #pragma unroll
            for (int j = 0; j < 4; j++) s[nt][j] = 0.f;
        #pragma unroll
        for (int ks = 0; ks < 8; ks++) {
            #pragma unroll
            for (int nt = 0; nt < 8; nt++) {
                unsigned b[2];
                b[0] = Kt[(nt * 8 + qr) * 68 + ks * 8 + qc];
                b[1] = Kt[(nt * 8 + qr) * 68 + ks * 8 + qc + 4];
                mma8(s[nt], qa[ks], b);
            }
        }

        // Online softmax: rows i=0 (qr), i=1 (qr+8); vals s[nt][2i],[2i+1]
        #pragma unroll
        for (int i = 0; i < 2; i++) {
            float mx = -1e30f;
            #pragma unroll
            for (int nt = 0; nt < 8; nt++)
                mx = fmaxf(mx, fmaxf(s[nt][2 * i], s[nt][2 * i + 1]));
            mx = fmaxf(mx, __shfl_xor_sync(0xffffffffu, mx, 1));
            mx = fmaxf(mx, __shfl_xor_sync(0xffffffffu, mx, 2));
            float mn = fmaxf(mrow[i], mx);
            float alpha = __expf(mrow[i] - mn);
            mrow[i] = mn;
            float rs = 0.f;
            #pragma unroll
            for (int nt = 0; nt < 8; nt++) {
                s[nt][2 * i]     = __expf(s[nt][2 * i] - mn);
                s[nt][2 * i + 1] = __expf(s[nt][2 * i + 1] - mn);
                rs += s[nt][2 * i] + s[nt][2 * i + 1];
            }
            rs += __shfl_xor_sync(0xffffffffu, rs, 1);
            rs += __shfl_xor_sync(0xffffffffu, rs, 2);
            lrow[i] = lrow[i] * alpha + rs;
            #pragma unroll
            for (int nt = 0; nt < 8; nt++) {
                o[nt][2 * i]     *= alpha;
                o[nt][2 * i + 1] *= alpha;
            }
        }

        // Store P (tf32) to smem — same-warp producer/consumer
        {
            int pr = warp * 16 + qr;
            #pragma unroll
            for (int nt = 0; nt < 8; nt++) {
                *(uint2*)&Ps[pr * 68 + nt * 8 + 2 * qc] =
                    make_uint2(f2tf(s[nt][0]), f2tf(s[nt][1]));
                *(uint2*)&Ps[(pr + 8) * 68 + nt * 8 + 2 * qc] =
                    make_uint2(f2tf(s[nt][2]), f2tf(s[nt][3]));
            }
        }
        __syncwarp();

        // O += P V
        #pragma unroll
        for (int ks = 0; ks < 8; ks++) {
            unsigned a[4];
            int ar = warp * 16 + qr;
            a[0] = Ps[ar * 68 + ks * 8 + qc];
            a[1] = Ps[(ar + 8) * 68 + ks * 8 + qc];
            a[2] = Ps[ar * 68 + ks * 8 + qc + 4];
            a[3] = Ps[(ar + 8) * 68 + ks * 8 + qc + 4];
            #pragma unroll
            for (int nt = 0; nt < 8; nt++) {
                unsigned b[2];
                b[0] = Vt[(nt * 8 + qr) * 68 + ks * 8 + qc];
                b[1] = Vt[(nt * 8 + qr) * 68 + ks * 8 + qc + 4];
                mma8(o[nt], a, b);
            }
        }
    }

    // Epilogue: normalize and write to g_X (B, N, C) with head offset
    const int bg = bh >> 3, hg = bh & 7;
    const float inv0 = 1.f / lrow[0];
    const float inv1 = 1.f / lrow[1];
    const int row0 = n0 + warp * 16 + qr;
    const int row1 = row0 + 8;
    float* X0 = &g_X[(bg * N_ + row0) * C_ + hg * D_];
    float* X1 = &g_X[(bg * N_ + row1) * C_ + hg * D_];
    #pragma unroll
    for (int nt = 0; nt < 8; nt++) {
        int col = nt * 8 + 2 * qc;
        *(float2*)&X0[col] = make_float2(o[nt][0] * inv0, o[nt][1] * inv0);
        *(float2*)&X1[col] = make_float2(o[nt][2] * inv1, o[nt][3] * inv1);
    }
}

// ---------------------------------------------------------------------------
// Output projection: out = X @ Wp^T + bp.  Same tiling as proj_qkv.
// ---------------------------------------------------------------------------
__global__ __launch_bounds__(256) void proj_out_kernel(
    const float* __restrict__ Wp, const float* __restrict__ bp,
    float* __restrict__ out)
{
    const int r0 = blockIdx.y * 128;
    const int cb = blockIdx.x * 64;

    __shared__ unsigned Asu[128 * 36];
    __shared__ unsigned Wsu[64 * 36];

    const int tid  = threadIdx.x;
    const int warp = tid >> 5;
    const int lane = tid & 31;
    const int qr = lane >> 2, qc = lane & 3;

    float acc[8][4];
    #pragma unroll
    for (int nt = 0; nt < 8; nt++)
        #pragma unroll
        for (int j = 0; j < 4; j++) acc[nt][j] = 0.f;

    for (int k0 = 0; k0 < C_; k0 += 32) {
        #pragma unroll
        for (int i = 0; i < 4; i++) {
            int idx = tid + i * 256;
            int row = idx >> 3, kq = (idx & 7) << 2;
            float4 v = *(const float4*)&g_X[(r0 + row) * C_ + k0 + kq];
            *(uint4*)&Asu[row * 36 + kq] =
                make_uint4(f2tf(v.x), f2tf(v.y), f2tf(v.z), f2tf(v.w));
        }
        #pragma unroll
        for (int i = 0; i < 2; i++) {
            int idx = tid + i * 256;
            int row = idx >> 3, kq = (idx & 7) << 2;
            float4 v = *(const float4*)&Wp[(cb + row) * C_ + k0 + kq];
            *(uint4*)&Wsu[row * 36 + kq] =
                make_uint4(f2tf(v.x), f2tf(v.y), f2tf(v.z), f2tf(v.w));
        }
        __syncthreads();

        #pragma unroll
        for (int ks = 0; ks < 4; ks++) {
            unsigned a[4];
            int ar = warp * 16 + qr;
            a[0] = Asu[ar * 36 + ks * 8 + qc];
            a[1] = Asu[(ar + 8) * 36 + ks * 8 + qc];
            a[2] = Asu[ar * 36 + ks * 8 + qc + 4];
            a[3] = Asu[(ar + 8) * 36 + ks * 8 + qc + 4];
            #pragma unroll
            for (int nt = 0; nt < 8; nt++) {
                unsigned b[2];
                b[0] = Wsu[(nt * 8 + qr) * 36 + ks * 8 + qc];
                b[1] = Wsu[(nt * 8 + qr) * 36 + ks * 8 + qc + 4];
                mma8(acc[nt], a, b);
            }
        }
        __syncthreads();
    }

    const int row0 = r0 + warp * 16 + qr;
    const int row1 = row0 + 8;
    #pragma unroll
    for (int nt = 0; nt < 8; nt++) {
        int col = cb + nt * 8 + 2 * qc;
        float b0v = bp[col], b1v = bp[col + 1];
        *(float2*)&out[row0 * C_ + col] =
            make_float2(acc[nt][0] + b0v, acc[nt][1] + b1v);
        *(float2*)&out[row1 * C_ + col] =
            make_float2(acc[nt][2] + b0v, acc[nt][3] + b1v);
    }
}

extern "C" void kernel_launch(void* const* d_in, const int* in_sizes, int n_in,
                              void* d_out, int out_size)
{
    const float* query = (const float*)d_in[0];
    const float* key   = (const float*)d_in[1];
    const float* value = (const float*)d_in[2];
    const float* Wq    = (const float*)d_in[3];
    const float* Wk    = (const float*)d_in[4];
    const float* Wv    = (const float*)d_in[5];
    const float* Wp    = (const float*)d_in[6];
    const float* bp    = (const float*)d_in[7];
    float* out = (float*)d_out;

    const int attn_smem = 4 * 64 * 68 * (int)sizeof(unsigned);  // 69632 B
    cudaFuncSetAttribute(attn_kernel,
                         cudaFuncAttributeMaxDynamicSharedMemorySize, attn_smem);

    dim3 blk(256);
    proj_qkv_kernel<<<dim3(8, 64, 3), blk>>>(query, key, value, Wq, Wk, Wv);
    attn_kernel<<<dim3(32, 16), blk, attn_smem>>>();
    proj_out_kernel<<<dim3(8, 64), blk>>>(Wp, bp, out);
}